// round 1
// baseline (speedup 1.0000x reference)
#include <cuda_runtime.h>
#include <math.h>

// Problem constants (fixed shapes per reference)
#define BATCH 4
#define SEQ   2048
#define DIM   1024     // D == KEY_DIM == VALUE_DIM
#define BETA  0.03125f // 1/sqrt(1024)

// GEMM tiling
#define BM 128
#define BN 128
#define BK 8
#define TM 8
#define TN 8

// Scratch (allocation-free rule: __device__ globals)
__device__ float g_q[BATCH * SEQ * DIM];                  // 32 MB
__device__ float g_k[BATCH * SEQ * DIM];                  // 32 MB
__device__ float g_v[BATCH * SEQ * DIM];                  // 32 MB
__device__ float g_s[(size_t)BATCH * SEQ * SEQ];          // 64 MB

// ---------------------------------------------------------------------------
// Generic 128x128x8 register-blocked SGEMM.
//   C[bz] = A[bz] @ B[bz] (+ bias)        (TRANSB=false: B is K x N row-major)
//   C[bz] = A[bz] @ B[bz]^T               (TRANSB=true : B is N x K row-major)
// Batch handled via blockIdx.z with element strides sA/sB/sC.
// All dims assumed multiples of the tile sizes (true for this problem).
// ---------------------------------------------------------------------------
template <bool TRANSB, bool HASBIAS>
__global__ __launch_bounds__(256) void gemm_k(
    const float* __restrict__ A, int sA,
    const float* __restrict__ B, int sB,
    const float* __restrict__ bias,
    float* __restrict__ C, int sC,
    int M, int N, int K)
{
    __shared__ float As[BK][BM];
    __shared__ float Bs[BK][BN];

    const int t  = threadIdx.x;
    const int bx = blockIdx.x;
    const int by = blockIdx.y;
    const int bz = blockIdx.z;

    const float* Ap = A + (size_t)bz * sA + (size_t)by * BM * K;
    const float* Bp = B + (size_t)bz * sB;
    float*       Cp = C + (size_t)bz * sC;

    // A-tile (and trans-B-tile) loader mapping: 128 rows x 8 cols, float4 each
    const int lRow = t >> 1;
    const int lCol = (t & 1) * 4;
    // non-trans B-tile loader mapping: 8 rows x 128 cols, float4 each
    const int nRow = t >> 5;
    const int nCol = (t & 31) * 4;
    // compute mapping: 16x16 thread grid, 8x8 micro-tile
    const int tr = (t >> 4) * TM;
    const int tc = (t & 15) * TN;

    float acc[TM][TN] = {};

    for (int k0 = 0; k0 < K; k0 += BK) {
        float4 a4 = *(const float4*)(Ap + (size_t)lRow * K + k0 + lCol);
        As[lCol + 0][lRow] = a4.x;
        As[lCol + 1][lRow] = a4.y;
        As[lCol + 2][lRow] = a4.z;
        As[lCol + 3][lRow] = a4.w;

        if (TRANSB) {
            float4 b4 = *(const float4*)(Bp + (size_t)(bx * BN + lRow) * K + k0 + lCol);
            Bs[lCol + 0][lRow] = b4.x;
            Bs[lCol + 1][lRow] = b4.y;
            Bs[lCol + 2][lRow] = b4.z;
            Bs[lCol + 3][lRow] = b4.w;
        } else {
            float4 b4 = *(const float4*)(Bp + (size_t)(k0 + nRow) * N + bx * BN + nCol);
            *(float4*)&Bs[nRow][nCol] = b4;
        }
        __syncthreads();

#pragma unroll
        for (int k = 0; k < BK; k++) {
            float ar[TM], br[TN];
            *(float4*)&ar[0] = *(const float4*)&As[k][tr];
            *(float4*)&ar[4] = *(const float4*)&As[k][tr + 4];
            *(float4*)&br[0] = *(const float4*)&Bs[k][tc];
            *(float4*)&br[4] = *(const float4*)&Bs[k][tc + 4];
#pragma unroll
            for (int i = 0; i < TM; i++)
#pragma unroll
                for (int j = 0; j < TN; j++)
                    acc[i][j] = fmaf(ar[i], br[j], acc[i][j]);
        }
        __syncthreads();
    }

#pragma unroll
    for (int i = 0; i < TM; i++) {
        const int row = by * BM + tr + i;
#pragma unroll
        for (int j = 0; j < TN; j += 4) {
            const int col = bx * BN + tc + j;
            float4 r;
            r.x = acc[i][j + 0];
            r.y = acc[i][j + 1];
            r.z = acc[i][j + 2];
            r.w = acc[i][j + 3];
            if (HASBIAS) {
                r.x += bias[col + 0];
                r.y += bias[col + 1];
                r.z += bias[col + 2];
                r.w += bias[col + 3];
            }
            *(float4*)(Cp + (size_t)row * N + col) = r;
        }
    }
}

// ---------------------------------------------------------------------------
// Row softmax over SEQ=2048 columns, with BETA scale folded in.
// One block (256 threads) per row; 8 elements per thread (2x float4).
// ---------------------------------------------------------------------------
__global__ __launch_bounds__(256) void softmax_rows(float* __restrict__ S)
{
    __shared__ float red[256];
    const int t = threadIdx.x;
    float* p = S + (size_t)blockIdx.x * SEQ;

    float4 v0 = *(float4*)(p + t * 4);
    float4 v1 = *(float4*)(p + 1024 + t * 4);
    v0.x *= BETA; v0.y *= BETA; v0.z *= BETA; v0.w *= BETA;
    v1.x *= BETA; v1.y *= BETA; v1.z *= BETA; v1.w *= BETA;

    float m = fmaxf(fmaxf(fmaxf(v0.x, v0.y), fmaxf(v0.z, v0.w)),
                    fmaxf(fmaxf(v1.x, v1.y), fmaxf(v1.z, v1.w)));
    red[t] = m;
    __syncthreads();
    for (int s = 128; s > 0; s >>= 1) {
        if (t < s) red[t] = fmaxf(red[t], red[t + s]);
        __syncthreads();
    }
    m = red[0];
    __syncthreads();

    v0.x = __expf(v0.x - m); v0.y = __expf(v0.y - m);
    v0.z = __expf(v0.z - m); v0.w = __expf(v0.w - m);
    v1.x = __expf(v1.x - m); v1.y = __expf(v1.y - m);
    v1.z = __expf(v1.z - m); v1.w = __expf(v1.w - m);

    float sum = (v0.x + v0.y) + (v0.z + v0.w) + (v1.x + v1.y) + (v1.z + v1.w);
    red[t] = sum;
    __syncthreads();
    for (int s = 128; s > 0; s >>= 1) {
        if (t < s) red[t] += red[t + s];
        __syncthreads();
    }
    const float inv = 1.0f / red[0];

    v0.x *= inv; v0.y *= inv; v0.z *= inv; v0.w *= inv;
    v1.x *= inv; v1.y *= inv; v1.z *= inv; v1.w *= inv;
    *(float4*)(p + t * 4) = v0;
    *(float4*)(p + 1024 + t * 4) = v1;
}

// ---------------------------------------------------------------------------
// Launch: proj(q,k,v) -> scores = q @ k^T -> softmax(beta*scores) -> out = A@v
// ---------------------------------------------------------------------------
extern "C" void kernel_launch(void* const* d_in, const int* in_sizes, int n_in,
                              void* d_out, int out_size)
{
    const float* query = (const float*)d_in[0];
    const float* key   = (const float*)d_in[1];
    const float* value = (const float*)d_in[2];
    const float* Wq    = (const float*)d_in[3];
    const float* bq    = (const float*)d_in[4];
    const float* Wk    = (const float*)d_in[5];
    const float* bk    = (const float*)d_in[6];
    const float* Wv    = (const float*)d_in[7];
    const float* bv    = (const float*)d_in[8];
    float* out = (float*)d_out;

    float *q, *k, *v, *s;
    cudaGetSymbolAddress((void**)&q, g_q);
    cudaGetSymbolAddress((void**)&k, g_k);
    cudaGetSymbolAddress((void**)&v, g_v);
    cudaGetSymbolAddress((void**)&s, g_s);

    // Projections: [8192,1024] @ [1024,1024] + bias
    {
        dim3 grid(DIM / BN, (BATCH * SEQ) / BM, 1);
        gemm_k<false, true><<<grid, 256>>>(query, 0, Wq, 0, bq, q, 0,
                                           BATCH * SEQ, DIM, DIM);
        gemm_k<false, true><<<grid, 256>>>(key,   0, Wk, 0, bk, k, 0,
                                           BATCH * SEQ, DIM, DIM);
        gemm_k<false, true><<<grid, 256>>>(value, 0, Wv, 0, bv, v, 0,
                                           BATCH * SEQ, DIM, DIM);
    }

    // Scores: per-batch q @ k^T  -> [S,S]
    {
        dim3 grid(SEQ / BN, SEQ / BM, BATCH);
        gemm_k<true, false><<<grid, 256>>>(q, SEQ * DIM, k, SEQ * DIM, nullptr,
                                           s, SEQ * SEQ, SEQ, SEQ, DIM);
    }

    // Softmax over rows (beta applied inside)
    softmax_rows<<<BATCH * SEQ, 256>>>(s);

    // Output: per-batch A @ v -> [S, DIM], written directly to d_out
    {
        dim3 grid(DIM / BN, SEQ / BM, BATCH);
        gemm_k<false, false><<<grid, 256>>>(s, SEQ * SEQ, v, SEQ * DIM, nullptr,
                                            out, SEQ * DIM, SEQ, DIM, SEQ);
    }
}

// round 2
// speedup vs baseline: 2.2942x; 2.2942x over previous
#include <cuda_runtime.h>
#include <cuda_bf16.h>
#include <math.h>
#include <stdint.h>

// Problem constants
#define BATCH 4
#define SEQ   2048
#define DIM   1024
#define BETA  0.03125f
#define MTOT  (BATCH * SEQ)        // 8192

// GEMM tile config
#define BM 128
#define BN 128
#define BKK 32                     // k per block tile (bf16 elems)
#define SSTR 40                    // smem row stride in bf16 elems (80B, conflict-free)
#define TILE_ELEMS (128 * SSTR)    // 5120 elems per tile
#define STAGE_ELEMS (4 * TILE_ELEMS) // Ahi,Alo,Bhi,Blo
#define SMEM_BYTES (2 * STAGE_ELEMS * 2) // 81920 B

// ---------------------------------------------------------------------------
// Scratch (__device__ globals; allocation-free rule)
// ---------------------------------------------------------------------------
__device__ __nv_bfloat16 g_x_h[MTOT * DIM];     // split input (reused q/k/v)
__device__ __nv_bfloat16 g_x_l[MTOT * DIM];
__device__ __nv_bfloat16 g_w_h[DIM * DIM];      // split+transposed weight (reused)
__device__ __nv_bfloat16 g_w_l[DIM * DIM];
__device__ float g_q[MTOT * DIM];
__device__ float g_k[MTOT * DIM];
__device__ float g_v[MTOT * DIM];
__device__ __nv_bfloat16 g_qh[MTOT * DIM], g_ql[MTOT * DIM];
__device__ __nv_bfloat16 g_kh[MTOT * DIM], g_kl[MTOT * DIM];
__device__ float g_s[(size_t)BATCH * SEQ * SEQ];
__device__ __nv_bfloat16 g_ah[(size_t)BATCH * SEQ * SEQ], g_al[(size_t)BATCH * SEQ * SEQ];
__device__ __nv_bfloat16 g_vth[MTOT * DIM], g_vtl[MTOT * DIM];  // v transposed [z][D][S]

// ---------------------------------------------------------------------------
// Helpers
// ---------------------------------------------------------------------------
__device__ __forceinline__ void cp16(__nv_bfloat16* smem_dst, const __nv_bfloat16* gsrc) {
    uint32_t s = (uint32_t)__cvta_generic_to_shared(smem_dst);
    asm volatile("cp.async.cg.shared.global [%0], [%1], 16;" :: "r"(s), "l"(gsrc));
}

#define MMA_BF16(d, a, b)                                                     \
    asm volatile(                                                             \
        "mma.sync.aligned.m16n8k16.row.col.f32.bf16.bf16.f32 "                \
        "{%0,%1,%2,%3}, {%4,%5,%6,%7}, {%8,%9}, {%0,%1,%2,%3};\n"             \
        : "+f"((d)[0]), "+f"((d)[1]), "+f"((d)[2]), "+f"((d)[3])              \
        : "r"((a)[0]), "r"((a)[1]), "r"((a)[2]), "r"((a)[3]),                 \
          "r"((b)[0]), "r"((b)[1]))

// ---------------------------------------------------------------------------
// Unified bf16 hi/lo 3-pass GEMM:  C[M,N] = A[M,K] @ B[N,K]^T (+bias)
//   A stored m x k (k contiguous), B stored n x k (k contiguous), C fp32.
//   C = Ah*Bh + Ah*Bl + Al*Bh, fp32 accumulate. All dims % tile == 0.
// ---------------------------------------------------------------------------
template <bool HASBIAS>
__global__ void __launch_bounds__(256, 1) gemm_bf16x3(
    const __nv_bfloat16* __restrict__ Ahi, const __nv_bfloat16* __restrict__ Alo, long sA,
    const __nv_bfloat16* __restrict__ Bhi, const __nv_bfloat16* __restrict__ Blo, long sB,
    const float* __restrict__ bias,
    float* __restrict__ C, long sC,
    int M, int N, int K)
{
    extern __shared__ __align__(16) __nv_bfloat16 smem[];

    const int t = threadIdx.x;
    const int lane = t & 31;
    const int warp = t >> 5;
    const int wm = warp >> 2;          // 0..1 -> 64 rows each
    const int wn = warp & 3;           // 0..3 -> 32 cols each
    const int r = lane >> 2;           // 0..7
    const int cq = lane & 3;           // 0..3

    const size_t aBase = (size_t)blockIdx.z * sA + (size_t)blockIdx.y * BM * K;
    const size_t bBase = (size_t)blockIdx.z * sB + (size_t)blockIdx.x * BN * K;

    float acc[4][4][4] = {};

    auto load_stage = [&](int st, int k0) {
        __nv_bfloat16* s = smem + st * STAGE_ELEMS;
#pragma unroll
        for (int i = 0; i < 2; i++) {
            int id = t + i * 256;
            int row = id >> 2;
            int ce = (id & 3) * 8;                   // elem col within 32
            size_t go = (size_t)row * K + k0 + ce;
            int so = row * SSTR + ce;
            cp16(s + so,                  Ahi + aBase + go);
            cp16(s + TILE_ELEMS + so,     Alo + aBase + go);
            cp16(s + 2 * TILE_ELEMS + so, Bhi + bBase + go);
            cp16(s + 3 * TILE_ELEMS + so, Blo + bBase + go);
        }
        asm volatile("cp.async.commit_group;" ::: "memory");
    };

    const int nk = K / BKK;
    load_stage(0, 0);

    for (int kt = 0; kt < nk; kt++) {
        if (kt + 1 < nk) {
            load_stage((kt + 1) & 1, (kt + 1) * BKK);
            asm volatile("cp.async.wait_group 1;" ::: "memory");
        } else {
            asm volatile("cp.async.wait_group 0;" ::: "memory");
        }
        __syncthreads();

        const uint32_t* sb = (const uint32_t*)(smem + (kt & 1) * STAGE_ELEMS);
        // 32-bit-unit offsets: tile = 2560 u32, row stride = 20 u32
#pragma unroll
        for (int kk = 0; kk < 2; kk++) {
            uint32_t ah[4][4], al[4][4], bh[4][2], bl[4][2];
#pragma unroll
            for (int mi = 0; mi < 4; mi++) {
                int row = wm * 64 + mi * 16 + r;
                int base = row * 20 + kk * 8 + cq;
                ah[mi][0] = sb[base];        ah[mi][1] = sb[base + 160];
                ah[mi][2] = sb[base + 4];    ah[mi][3] = sb[base + 164];
                al[mi][0] = sb[2560 + base];       al[mi][1] = sb[2560 + base + 160];
                al[mi][2] = sb[2560 + base + 4];   al[mi][3] = sb[2560 + base + 164];
            }
#pragma unroll
            for (int ni = 0; ni < 4; ni++) {
                int row = wn * 32 + ni * 8 + r;
                int base = 5120 + row * 20 + kk * 8 + cq;
                bh[ni][0] = sb[base];        bh[ni][1] = sb[base + 4];
                bl[ni][0] = sb[base + 2560]; bl[ni][1] = sb[base + 2560 + 4];
            }
#pragma unroll
            for (int mi = 0; mi < 4; mi++)
#pragma unroll
                for (int ni = 0; ni < 4; ni++) {
                    MMA_BF16(acc[mi][ni], ah[mi], bh[ni]);
                    MMA_BF16(acc[mi][ni], ah[mi], bl[ni]);
                    MMA_BF16(acc[mi][ni], al[mi], bh[ni]);
                }
        }
        __syncthreads();
    }

    // Epilogue
    float* Cp = C + (size_t)blockIdx.z * sC;
    const int row0 = blockIdx.y * BM + wm * 64;
    const int col0 = blockIdx.x * BN + wn * 32;
#pragma unroll
    for (int mi = 0; mi < 4; mi++) {
#pragma unroll
        for (int ni = 0; ni < 4; ni++) {
            int rr = row0 + mi * 16 + r;
            int cc = col0 + ni * 8 + 2 * cq;
            float b0 = 0.f, b1 = 0.f;
            if (HASBIAS) { b0 = bias[cc]; b1 = bias[cc + 1]; }
            float2 v0 = make_float2(acc[mi][ni][0] + b0, acc[mi][ni][1] + b1);
            float2 v1 = make_float2(acc[mi][ni][2] + b0, acc[mi][ni][3] + b1);
            *(float2*)(Cp + (size_t)rr * N + cc) = v0;
            *(float2*)(Cp + (size_t)(rr + 8) * N + cc) = v1;
        }
    }
}

// ---------------------------------------------------------------------------
// Elementwise split: fp32 -> hi/lo bf16 (same layout)
// ---------------------------------------------------------------------------
__global__ void __launch_bounds__(256) split_kernel(
    const float* __restrict__ x, __nv_bfloat16* __restrict__ hi,
    __nv_bfloat16* __restrict__ lo, int n4)
{
    int i = blockIdx.x * 256 + threadIdx.x;
    if (i >= n4) return;
    float4 v = ((const float4*)x)[i];
    __nv_bfloat16 hx = __float2bfloat16(v.x), hy = __float2bfloat16(v.y);
    __nv_bfloat16 hz = __float2bfloat16(v.z), hw = __float2bfloat16(v.w);
    __nv_bfloat162 h0; h0.x = hx; h0.y = hy;
    __nv_bfloat162 h1; h1.x = hz; h1.y = hw;
    __nv_bfloat162 l0, l1;
    l0.x = __float2bfloat16(v.x - __bfloat162float(hx));
    l0.y = __float2bfloat16(v.y - __bfloat162float(hy));
    l1.x = __float2bfloat16(v.z - __bfloat162float(hz));
    l1.y = __float2bfloat16(v.w - __bfloat162float(hw));
    ((__nv_bfloat162*)hi)[2 * i]     = h0;
    ((__nv_bfloat162*)hi)[2 * i + 1] = h1;
    ((__nv_bfloat162*)lo)[2 * i]     = l0;
    ((__nv_bfloat162*)lo)[2 * i + 1] = l1;
}

// ---------------------------------------------------------------------------
// Split + transpose: x[z][R][C] fp32 -> hi/lo[z][C][R] bf16
// block (32,8), grid (C/32, R/32, z)
// ---------------------------------------------------------------------------
__global__ void __launch_bounds__(256) split_transpose(
    const float* __restrict__ x, __nv_bfloat16* __restrict__ hi,
    __nv_bfloat16* __restrict__ lo, int R, int Ccols)
{
    __shared__ float tile[32][33];
    const size_t zo = (size_t)blockIdx.z * R * Ccols;
    const float* xp = x + zo;
    const int c0 = blockIdx.x * 32, r0 = blockIdx.y * 32;
    const int tx = threadIdx.x, ty = threadIdx.y;
#pragma unroll
    for (int i = 0; i < 32; i += 8)
        tile[ty + i][tx] = xp[(size_t)(r0 + ty + i) * Ccols + c0 + tx];
    __syncthreads();
#pragma unroll
    for (int i = 0; i < 32; i += 8) {
        float v = tile[tx][ty + i];
        __nv_bfloat16 h = __float2bfloat16(v);
        __nv_bfloat16 l = __float2bfloat16(v - __bfloat162float(h));
        size_t o = zo + (size_t)(c0 + ty + i) * R + r0 + tx;
        hi[o] = h;
        lo[o] = l;
    }
}

// ---------------------------------------------------------------------------
// Row softmax over SEQ columns with BETA folded in (unchanged from R1)
// ---------------------------------------------------------------------------
__global__ void __launch_bounds__(256) softmax_rows(float* __restrict__ S)
{
    __shared__ float red[256];
    const int t = threadIdx.x;
    float* p = S + (size_t)blockIdx.x * SEQ;

    float4 v0 = *(float4*)(p + t * 4);
    float4 v1 = *(float4*)(p + 1024 + t * 4);
    v0.x *= BETA; v0.y *= BETA; v0.z *= BETA; v0.w *= BETA;
    v1.x *= BETA; v1.y *= BETA; v1.z *= BETA; v1.w *= BETA;

    float m = fmaxf(fmaxf(fmaxf(v0.x, v0.y), fmaxf(v0.z, v0.w)),
                    fmaxf(fmaxf(v1.x, v1.y), fmaxf(v1.z, v1.w)));
    red[t] = m;
    __syncthreads();
    for (int s = 128; s > 0; s >>= 1) {
        if (t < s) red[t] = fmaxf(red[t], red[t + s]);
        __syncthreads();
    }
    m = red[0];
    __syncthreads();

    v0.x = __expf(v0.x - m); v0.y = __expf(v0.y - m);
    v0.z = __expf(v0.z - m); v0.w = __expf(v0.w - m);
    v1.x = __expf(v1.x - m); v1.y = __expf(v1.y - m);
    v1.z = __expf(v1.z - m); v1.w = __expf(v1.w - m);

    float sum = (v0.x + v0.y) + (v0.z + v0.w) + (v1.x + v1.y) + (v1.z + v1.w);
    red[t] = sum;
    __syncthreads();
    for (int s = 128; s > 0; s >>= 1) {
        if (t < s) red[t] += red[t + s];
        __syncthreads();
    }
    const float inv = 1.0f / red[0];

    v0.x *= inv; v0.y *= inv; v0.z *= inv; v0.w *= inv;
    v1.x *= inv; v1.y *= inv; v1.z *= inv; v1.w *= inv;
    *(float4*)(p + t * 4) = v0;
    *(float4*)(p + 1024 + t * 4) = v1;
}

// ---------------------------------------------------------------------------
// Launch
// ---------------------------------------------------------------------------
extern "C" void kernel_launch(void* const* d_in, const int* in_sizes, int n_in,
                              void* d_out, int out_size)
{
    const float* query = (const float*)d_in[0];
    const float* key   = (const float*)d_in[1];
    const float* value = (const float*)d_in[2];
    const float* Wq    = (const float*)d_in[3];
    const float* bq    = (const float*)d_in[4];
    const float* Wk    = (const float*)d_in[5];
    const float* bk    = (const float*)d_in[6];
    const float* Wv    = (const float*)d_in[7];
    const float* bv    = (const float*)d_in[8];
    float* out = (float*)d_out;

    __nv_bfloat16 *xh, *xl, *wh, *wl, *qh, *ql, *kh, *kl, *ah, *al, *vth, *vtl;
    float *qf, *kf, *vf, *sf;
    cudaGetSymbolAddress((void**)&xh, g_x_h);
    cudaGetSymbolAddress((void**)&xl, g_x_l);
    cudaGetSymbolAddress((void**)&wh, g_w_h);
    cudaGetSymbolAddress((void**)&wl, g_w_l);
    cudaGetSymbolAddress((void**)&qf, g_q);
    cudaGetSymbolAddress((void**)&kf, g_k);
    cudaGetSymbolAddress((void**)&vf, g_v);
    cudaGetSymbolAddress((void**)&qh, g_qh);
    cudaGetSymbolAddress((void**)&ql, g_ql);
    cudaGetSymbolAddress((void**)&kh, g_kh);
    cudaGetSymbolAddress((void**)&kl, g_kl);
    cudaGetSymbolAddress((void**)&sf, g_s);
    cudaGetSymbolAddress((void**)&ah, g_ah);
    cudaGetSymbolAddress((void**)&al, g_al);
    cudaGetSymbolAddress((void**)&vth, g_vth);
    cudaGetSymbolAddress((void**)&vtl, g_vtl);

    cudaFuncSetAttribute((const void*)gemm_bf16x3<true>,
                         cudaFuncAttributeMaxDynamicSharedMemorySize, SMEM_BYTES);
    cudaFuncSetAttribute((const void*)gemm_bf16x3<false>,
                         cudaFuncAttributeMaxDynamicSharedMemorySize, SMEM_BYTES);

    const int nIn4 = MTOT * DIM / 4;
    const dim3 projGrid(DIM / BN, MTOT / BM, 1);
    const dim3 wtGrid(DIM / 32, DIM / 32, 1);

    // ---- Projections (reuse x/w split buffers sequentially) ----
    split_transpose<<<wtGrid, dim3(32, 8)>>>(Wq, wh, wl, DIM, DIM);
    split_kernel<<<nIn4 / 256, 256>>>(query, xh, xl, nIn4);
    gemm_bf16x3<true><<<projGrid, 256, SMEM_BYTES>>>(xh, xl, 0, wh, wl, 0, bq,
                                                     qf, 0, MTOT, DIM, DIM);

    split_transpose<<<wtGrid, dim3(32, 8)>>>(Wk, wh, wl, DIM, DIM);
    split_kernel<<<nIn4 / 256, 256>>>(key, xh, xl, nIn4);
    gemm_bf16x3<true><<<projGrid, 256, SMEM_BYTES>>>(xh, xl, 0, wh, wl, 0, bk,
                                                     kf, 0, MTOT, DIM, DIM);

    split_transpose<<<wtGrid, dim3(32, 8)>>>(Wv, wh, wl, DIM, DIM);
    split_kernel<<<nIn4 / 256, 256>>>(value, xh, xl, nIn4);
    gemm_bf16x3<true><<<projGrid, 256, SMEM_BYTES>>>(xh, xl, 0, wh, wl, 0, bv,
                                                     vf, 0, MTOT, DIM, DIM);

    // ---- Scores: s[z] = q[z] @ k[z]^T ----
    split_kernel<<<nIn4 / 256, 256>>>(qf, qh, ql, nIn4);
    split_kernel<<<nIn4 / 256, 256>>>(kf, kh, kl, nIn4);
    {
        dim3 grid(SEQ / BN, SEQ / BM, BATCH);
        gemm_bf16x3<false><<<grid, 256, SMEM_BYTES>>>(
            qh, ql, (long)SEQ * DIM, kh, kl, (long)SEQ * DIM, nullptr,
            sf, (long)SEQ * SEQ, SEQ, SEQ, DIM);
    }

    // ---- Softmax (beta folded) ----
    softmax_rows<<<BATCH * SEQ, 256>>>(sf);

    // ---- Out: out[z] = A[z] @ v[z]  (v transposed to [D][S] for n x k) ----
    {
        int nS4 = BATCH * SEQ * SEQ / 4;
        split_kernel<<<nS4 / 256, 256>>>(sf, ah, al, nS4);
        split_transpose<<<dim3(DIM / 32, SEQ / 32, BATCH), dim3(32, 8)>>>(
            vf, vth, vtl, SEQ, DIM);
        dim3 grid(DIM / BN, SEQ / BM, BATCH);
        gemm_bf16x3<false><<<grid, 256, SMEM_BYTES>>>(
            ah, al, (long)SEQ * SEQ, vth, vtl, (long)SEQ * DIM, nullptr,
            out, (long)SEQ * DIM, SEQ, DIM, SEQ);
    }
}

// round 4
// speedup vs baseline: 3.4714x; 1.5132x over previous
#include <cuda_runtime.h>
#include <cuda_bf16.h>
#include <stdint.h>
#include <math.h>

// Problem constants
#define BATCH 4
#define SEQ   2048
#define DIM   1024
#define MTOT  (BATCH * SEQ)      // 8192
#define BETA  0.03125f

// ---------------------------------------------------------------------------
// Arch-feature gate: tcgen05 exists only on arch-specific (a/f) targets.
// Base sm_103 PTX passes compile the mma.sync fallback instead.
// ---------------------------------------------------------------------------
#if defined(__CUDA_ARCH__) && \
    (defined(__CUDA_ARCH_FEAT_SM103_ALL) || defined(__CUDA_ARCH_FEAT_SM100_ALL) || \
     defined(__CUDA_ARCH_SPECIFIC__) || defined(__CUDA_ARCH_FAMILY_SPECIFIC__))
#define HAS_TCGEN05 1
#else
#define HAS_TCGEN05 0
#endif

// tcgen05 path: 128x128 tile, K-chunk 64 bf16 (128B rows, SW128)
#define KC       64
#define TB       16384                   // one tile: 128 rows * 128 B
#define STAGE_B  (4 * TB)                // Ah | Al | Bh | Bl = 64 KB
#define CTRL_OFF (2 * STAGE_B)
#define SMEM_TOTAL (CTRL_OFF + 64)
#define IDESC 0x8200490u                 // F32 acc, bf16 a/b, N=128, M=128

// fallback path (R2): 128x128 tile, K-chunk 32, padded rows (40 elems)
#define FSSTR 40
#define FTILE (128 * FSSTR)              // 5120 bf16 elems
#define FSTAGE (4 * FTILE)

// ---------------------------------------------------------------------------
// Scratch (__device__ globals; allocation-free rule)
// ---------------------------------------------------------------------------
__device__ __align__(16) __nv_bfloat16 g_xh[MTOT * DIM], g_xl[MTOT * DIM];
__device__ __align__(16) __nv_bfloat16 g_wh[DIM * DIM],  g_wl[DIM * DIM];
__device__ __align__(16) __nv_bfloat16 g_qh[MTOT * DIM], g_ql[MTOT * DIM];
__device__ __align__(16) __nv_bfloat16 g_kh[MTOT * DIM], g_kl[MTOT * DIM];
__device__ __align__(16) float         g_vf[MTOT * DIM];
__device__ __align__(16) __nv_bfloat16 g_vth[MTOT * DIM], g_vtl[MTOT * DIM];
__device__ __align__(16) float         g_sf[(size_t)BATCH * SEQ * SEQ];
__device__ __align__(16) __nv_bfloat16 g_ah[(size_t)BATCH * SEQ * SEQ];
__device__ __align__(16) __nv_bfloat16 g_al[(size_t)BATCH * SEQ * SEQ];

// ---------------------------------------------------------------------------
// Common helpers
// ---------------------------------------------------------------------------
__device__ __forceinline__ uint32_t s2u(const void* p) {
    return (uint32_t)__cvta_generic_to_shared(p);
}
__device__ __forceinline__ void cp16(uint32_t s, const void* g) {
    asm volatile("cp.async.cg.shared.global [%0], [%1], 16;" :: "r"(s), "l"(g));
}
__device__ __forceinline__ void bf_split2(float a, float b,
                                          __nv_bfloat162& hh, __nv_bfloat162& ll) {
    __nv_bfloat16 ha = __float2bfloat16(a), hb = __float2bfloat16(b);
    hh.x = ha; hh.y = hb;
    ll.x = __float2bfloat16(a - __bfloat162float(ha));
    ll.y = __float2bfloat16(b - __bfloat162float(hb));
}

#if HAS_TCGEN05
__device__ __forceinline__ bool elect1() {
    uint32_t p;
    asm volatile("{\n\t.reg .pred p;\n\telect.sync _|p, 0xFFFFFFFF;\n\t"
                 "selp.b32 %0, 1, 0, p;\n\t}" : "=r"(p));
    return p != 0;
}
__device__ __forceinline__ uint32_t swz(uint32_t o) {  // SW128 swizzle
    return o ^ ((o >> 3) & 0x70);
}
__device__ __forceinline__ uint64_t mk_desc(uint32_t addr) {
    return ((uint64_t)2 << 61) | ((uint64_t)1 << 46) | ((uint64_t)64 << 32) |
           ((uint64_t)1 << 16) | ((uint64_t)(addr >> 4) & 0x3FFF);
}
__device__ __forceinline__ void mma_ss(uint32_t d, uint64_t a, uint64_t b, uint32_t en) {
    asm volatile(
        "{\n\t.reg .pred p;\n\tsetp.ne.u32 p, %4, 0;\n\t"
        "tcgen05.mma.cta_group::1.kind::f16 [%0], %1, %2, %3, {%5,%5,%5,%5}, p;\n\t}"
        :: "r"(d), "l"(a), "l"(b), "r"(IDESC), "r"(en), "r"(0u) : "memory");
}
__device__ __forceinline__ void bar_wait(uint32_t mbar, int parity) {
    asm volatile(
        "{\n\t.reg .pred P;\n\t"
        "W%=:\n\t"
        "mbarrier.try_wait.parity.acquire.cta.shared::cta.b64 P, [%0], %1, 0x989680;\n\t"
        "@P bra D%=;\n\t"
        "bra W%=;\n\t"
        "D%=:\n\t}"
        :: "r"(mbar), "r"(parity) : "memory");
}
__device__ __forceinline__ void ldtm_x32(uint32_t* r, uint32_t a) {
    asm volatile(
        "tcgen05.ld.sync.aligned.32x32b.x32.b32 "
        "{%0,%1,%2,%3,%4,%5,%6,%7,%8,%9,%10,%11,%12,%13,%14,%15,"
        "%16,%17,%18,%19,%20,%21,%22,%23,%24,%25,%26,%27,%28,%29,%30,%31}, [%32];"
        : "=r"(r[0]), "=r"(r[1]), "=r"(r[2]), "=r"(r[3]), "=r"(r[4]), "=r"(r[5]),
          "=r"(r[6]), "=r"(r[7]), "=r"(r[8]), "=r"(r[9]), "=r"(r[10]), "=r"(r[11]),
          "=r"(r[12]), "=r"(r[13]), "=r"(r[14]), "=r"(r[15]), "=r"(r[16]), "=r"(r[17]),
          "=r"(r[18]), "=r"(r[19]), "=r"(r[20]), "=r"(r[21]), "=r"(r[22]), "=r"(r[23]),
          "=r"(r[24]), "=r"(r[25]), "=r"(r[26]), "=r"(r[27]), "=r"(r[28]), "=r"(r[29]),
          "=r"(r[30]), "=r"(r[31])
        : "r"(a));
}
#else
#define MMA_BF16(d, a, b)                                                     \
    asm volatile(                                                             \
        "mma.sync.aligned.m16n8k16.row.col.f32.bf16.bf16.f32 "                \
        "{%0,%1,%2,%3}, {%4,%5,%6,%7}, {%8,%9}, {%0,%1,%2,%3};\n"             \
        : "+f"((d)[0]), "+f"((d)[1]), "+f"((d)[2]), "+f"((d)[3])              \
        : "r"((a)[0]), "r"((a)[1]), "r"((a)[2]), "r"((a)[3]),                 \
          "r"((b)[0]), "r"((b)[1]))
#endif

// ---------------------------------------------------------------------------
// GEMM: C[M,N] = A[M,K] @ B[N,K]^T (+bias), bf16 hi/lo 3-pass, fp32 accum.
// EPI: 0 = fp32, 1 = fp32 + bias, 2 = bf16 hi/lo split + bias
// Grid: (N/128, M/128, batch). ldc = N.
// ---------------------------------------------------------------------------
template <int EPI>
__global__ void __launch_bounds__(256, 1)
gemm_tc(const __nv_bfloat16* __restrict__ Ahi, const __nv_bfloat16* __restrict__ Alo, long sA,
        const __nv_bfloat16* __restrict__ Bhi, const __nv_bfloat16* __restrict__ Blo, long sB,
        const float* __restrict__ bias,
        float* __restrict__ C, __nv_bfloat16* __restrict__ Chi,
        __nv_bfloat16* __restrict__ Clo, long sC,
        int K, int ldc)
{
#if HAS_TCGEN05
    // ======================= tcgen05 path =======================
    extern __shared__ __align__(1024) char smem[];
    const uint32_t sbase = s2u(smem);
    const uint32_t ctrl = sbase + CTRL_OFF;   // [0]=tmem ptr, [8]=bar0, [16]=bar1

    const int t = threadIdx.x;
    const int warp = t >> 5;
    const int lane = t & 31;

    if (warp == 0) {
        asm volatile("tcgen05.alloc.cta_group::1.sync.aligned.shared::cta.b32 [%0], %1;"
                     :: "r"(ctrl), "r"(128u) : "memory");
    }
    if (t == 0) {
        asm volatile("mbarrier.init.shared.b64 [%0], 1;" :: "r"(ctrl + 8) : "memory");
        asm volatile("mbarrier.init.shared.b64 [%0], 1;" :: "r"(ctrl + 16) : "memory");
    }
    __syncthreads();
    uint32_t tmem;
    asm volatile("ld.shared.b32 %0, [%1];" : "=r"(tmem) : "r"(ctrl));

    const size_t aBase = (size_t)blockIdx.z * sA + (size_t)blockIdx.y * 128 * K;
    const size_t bBase = (size_t)blockIdx.z * sB + (size_t)blockIdx.x * 128 * K;

    auto load_stage = [&](int st, int k0) {
        const uint32_t so = sbase + st * STAGE_B;
#pragma unroll
        for (int i = 0; i < 4; i++) {
            int c = t * 4 + i;             // 0..1023 16B-chunk id
            int row = c >> 3;              // 0..127
            int col = c & 7;               // 16B chunk within 128B row
            uint32_t sw = swz(row * 128 + col * 16);
            size_t ga = aBase + (size_t)row * K + k0 + col * 8;
            size_t gb = bBase + (size_t)row * K + k0 + col * 8;
            cp16(so + sw,           Ahi + ga);
            cp16(so + TB + sw,      Alo + ga);
            cp16(so + 2 * TB + sw,  Bhi + gb);
            cp16(so + 3 * TB + sw,  Blo + gb);
        }
        asm volatile("cp.async.commit_group;" ::: "memory");
    };

    const int nk = K / KC;
    int ph0 = 0, ph1 = 0;
    load_stage(0, 0);

    for (int kt = 0; kt < nk; kt++) {
        const int s = kt & 1;
        if (kt + 1 < nk) {
            if (kt >= 1) {
                if (s) { bar_wait(ctrl + 8,  ph0); ph0 ^= 1; }
                else   { bar_wait(ctrl + 16, ph1); ph1 ^= 1; }
            }
            load_stage(1 - s, (kt + 1) * KC);
            asm volatile("cp.async.wait_group 1;" ::: "memory");
        } else {
            asm volatile("cp.async.wait_group 0;" ::: "memory");
        }
        asm volatile("fence.proxy.async.shared::cta;" ::: "memory");
        __syncthreads();

        if (warp == 0 && elect1()) {
            const uint32_t sa = sbase + s * STAGE_B;
            const uint64_t dAh = mk_desc(sa);
            const uint64_t dAl = mk_desc(sa + TB);
            const uint64_t dBh = mk_desc(sa + 2 * TB);
            const uint64_t dBl = mk_desc(sa + 3 * TB);
#pragma unroll
            for (int k = 0; k < 4; k++) {
                mma_ss(tmem, dAh + k * 2, dBh + k * 2, !(kt == 0 && k == 0));
                mma_ss(tmem, dAh + k * 2, dBl + k * 2, 1u);
                mma_ss(tmem, dAl + k * 2, dBh + k * 2, 1u);
            }
            asm volatile(
                "tcgen05.commit.cta_group::1.mbarrier::arrive::one.shared::cluster.b64 [%0];"
                :: "r"(ctrl + 8 + s * 8) : "memory");
        }
    }

    if ((nk - 1) & 1) bar_wait(ctrl + 16, ph1);
    else              bar_wait(ctrl + 8,  ph0);
    asm volatile("tcgen05.fence::after_thread_sync;" ::: "memory");

    {
        const int sub = warp & 3;            // TMEM subpartition = warp % 4
        const int half = warp >> 2;          // 64-col half
        const int row = blockIdx.y * 128 + sub * 32 + lane;
        const int gcol0 = blockIdx.x * 128 + half * 64;

        uint32_t r[64];
        ldtm_x32(r,      tmem + half * 64);
        ldtm_x32(r + 32, tmem + half * 64 + 32);
        asm volatile("tcgen05.wait::ld.sync.aligned;" ::: "memory");

        if (EPI == 2) {
            const size_t o = (size_t)row * ldc + gcol0;
#pragma unroll
            for (int j = 0; j < 64; j += 2) {
                float v0 = __uint_as_float(r[j])     + bias[gcol0 + j];
                float v1 = __uint_as_float(r[j + 1]) + bias[gcol0 + j + 1];
                __nv_bfloat162 hh, ll;
                bf_split2(v0, v1, hh, ll);
                *(__nv_bfloat162*)(Chi + o + j) = hh;
                *(__nv_bfloat162*)(Clo + o + j) = ll;
            }
        } else {
            float* cp = C + (size_t)blockIdx.z * sC + (size_t)row * ldc + gcol0;
#pragma unroll
            for (int j = 0; j < 64; j += 4) {
                float4 v;
                v.x = __uint_as_float(r[j]);
                v.y = __uint_as_float(r[j + 1]);
                v.z = __uint_as_float(r[j + 2]);
                v.w = __uint_as_float(r[j + 3]);
                if (EPI == 1) {
                    v.x += bias[gcol0 + j];
                    v.y += bias[gcol0 + j + 1];
                    v.z += bias[gcol0 + j + 2];
                    v.w += bias[gcol0 + j + 3];
                }
                *(float4*)(cp + j) = v;
            }
        }
    }

    __syncthreads();
    if (warp == 0) {
        asm volatile("tcgen05.relinquish_alloc_permit.cta_group::1.sync.aligned;" ::: "memory");
        asm volatile("tcgen05.dealloc.cta_group::1.sync.aligned.b32 %0, %1;"
                     :: "r"(tmem), "r"(128u));
    }

#else
    // ======================= mma.sync fallback (R2, measured 1363.8us) =====
    extern __shared__ __align__(16) __nv_bfloat16 fsm[];

    const int t = threadIdx.x;
    const int lane = t & 31;
    const int warp = t >> 5;
    const int wm = warp >> 2;
    const int wn = warp & 3;
    const int r = lane >> 2;
    const int cq = lane & 3;
    const int N = ldc;

    const size_t aBase = (size_t)blockIdx.z * sA + (size_t)blockIdx.y * 128 * K;
    const size_t bBase = (size_t)blockIdx.z * sB + (size_t)blockIdx.x * 128 * K;

    float acc[4][4][4] = {};

    auto load_stage = [&](int st, int k0) {
        __nv_bfloat16* s = fsm + st * FSTAGE;
#pragma unroll
        for (int i = 0; i < 2; i++) {
            int id = t + i * 256;
            int row = id >> 2;
            int ce = (id & 3) * 8;
            size_t goA = aBase + (size_t)row * K + k0 + ce;
            size_t goB = bBase + (size_t)row * K + k0 + ce;
            int so = row * FSSTR + ce;
            cp16(s2u(s + so),              Ahi + goA);
            cp16(s2u(s + FTILE + so),      Alo + goA);
            cp16(s2u(s + 2 * FTILE + so),  Bhi + goB);
            cp16(s2u(s + 3 * FTILE + so),  Blo + goB);
        }
        asm volatile("cp.async.commit_group;" ::: "memory");
    };

    const int nk = K / 32;
    load_stage(0, 0);

    for (int kt = 0; kt < nk; kt++) {
        if (kt + 1 < nk) {
            load_stage((kt + 1) & 1, (kt + 1) * 32);
            asm volatile("cp.async.wait_group 1;" ::: "memory");
        } else {
            asm volatile("cp.async.wait_group 0;" ::: "memory");
        }
        __syncthreads();

        const uint32_t* sb = (const uint32_t*)(fsm + (kt & 1) * FSTAGE);
#pragma unroll
        for (int kk = 0; kk < 2; kk++) {
            uint32_t ah[4][4], al[4][4], bh[4][2], bl[4][2];
#pragma unroll
            for (int mi = 0; mi < 4; mi++) {
                int row = wm * 64 + mi * 16 + r;
                int base = row * 20 + kk * 8 + cq;
                ah[mi][0] = sb[base];        ah[mi][1] = sb[base + 160];
                ah[mi][2] = sb[base + 4];    ah[mi][3] = sb[base + 164];
                al[mi][0] = sb[2560 + base];       al[mi][1] = sb[2560 + base + 160];
                al[mi][2] = sb[2560 + base + 4];   al[mi][3] = sb[2560 + base + 164];
            }
#pragma unroll
            for (int ni = 0; ni < 4; ni++) {
                int row = wn * 32 + ni * 8 + r;
                int base = 5120 + row * 20 + kk * 8 + cq;
                bh[ni][0] = sb[base];        bh[ni][1] = sb[base + 4];
                bl[ni][0] = sb[base + 2560]; bl[ni][1] = sb[base + 2560 + 4];
            }
#pragma unroll
            for (int mi = 0; mi < 4; mi++)
#pragma unroll
                for (int ni = 0; ni < 4; ni++) {
                    MMA_BF16(acc[mi][ni], ah[mi], bh[ni]);
                    MMA_BF16(acc[mi][ni], ah[mi], bl[ni]);
                    MMA_BF16(acc[mi][ni], al[mi], bh[ni]);
                }
        }
        __syncthreads();
    }

    const int row0 = blockIdx.y * 128 + wm * 64;
    const int col0 = blockIdx.x * 128 + wn * 32;
#pragma unroll
    for (int mi = 0; mi < 4; mi++) {
#pragma unroll
        for (int ni = 0; ni < 4; ni++) {
            int rr = row0 + mi * 16 + r;
            int cc = col0 + ni * 8 + 2 * cq;
            if (EPI == 2) {
                float b0 = bias[cc], b1 = bias[cc + 1];
                __nv_bfloat162 hh, ll;
                bf_split2(acc[mi][ni][0] + b0, acc[mi][ni][1] + b1, hh, ll);
                *(__nv_bfloat162*)(Chi + (size_t)rr * N + cc) = hh;
                *(__nv_bfloat162*)(Clo + (size_t)rr * N + cc) = ll;
                bf_split2(acc[mi][ni][2] + b0, acc[mi][ni][3] + b1, hh, ll);
                *(__nv_bfloat162*)(Chi + (size_t)(rr + 8) * N + cc) = hh;
                *(__nv_bfloat162*)(Clo + (size_t)(rr + 8) * N + cc) = ll;
            } else {
                float b0 = 0.f, b1 = 0.f;
                if (EPI == 1) { b0 = bias[cc]; b1 = bias[cc + 1]; }
                float* Cp = C + (size_t)blockIdx.z * sC;
                float2 v0 = make_float2(acc[mi][ni][0] + b0, acc[mi][ni][1] + b1);
                float2 v1 = make_float2(acc[mi][ni][2] + b0, acc[mi][ni][3] + b1);
                *(float2*)(Cp + (size_t)rr * N + cc) = v0;
                *(float2*)(Cp + (size_t)(rr + 8) * N + cc) = v1;
            }
        }
    }
#endif
}

// ---------------------------------------------------------------------------
// Elementwise split: fp32 -> hi/lo bf16
// ---------------------------------------------------------------------------
__global__ void __launch_bounds__(256) split_kernel(
    const float* __restrict__ x, __nv_bfloat16* __restrict__ hi,
    __nv_bfloat16* __restrict__ lo, int n4)
{
    int i = blockIdx.x * 256 + threadIdx.x;
    if (i >= n4) return;
    float4 v = ((const float4*)x)[i];
    __nv_bfloat162 h0, l0, h1, l1;
    bf_split2(v.x, v.y, h0, l0);
    bf_split2(v.z, v.w, h1, l1);
    ((__nv_bfloat162*)hi)[2 * i]     = h0;
    ((__nv_bfloat162*)hi)[2 * i + 1] = h1;
    ((__nv_bfloat162*)lo)[2 * i]     = l0;
    ((__nv_bfloat162*)lo)[2 * i + 1] = l1;
}

// ---------------------------------------------------------------------------
// Split + transpose: x[z][R][C] fp32 -> hi/lo[z][C][R] bf16
// ---------------------------------------------------------------------------
__global__ void __launch_bounds__(256) split_transpose(
    const float* __restrict__ x, __nv_bfloat16* __restrict__ hi,
    __nv_bfloat16* __restrict__ lo, int R, int Ccols)
{
    __shared__ float tile[32][33];
    const size_t zo = (size_t)blockIdx.z * R * Ccols;
    const float* xp = x + zo;
    const int c0 = blockIdx.x * 32, r0 = blockIdx.y * 32;
    const int tx = threadIdx.x, ty = threadIdx.y;
#pragma unroll
    for (int i = 0; i < 32; i += 8)
        tile[ty + i][tx] = xp[(size_t)(r0 + ty + i) * Ccols + c0 + tx];
    __syncthreads();
#pragma unroll
    for (int i = 0; i < 32; i += 8) {
        float v = tile[tx][ty + i];
        __nv_bfloat16 h = __float2bfloat16(v);
        __nv_bfloat16 l = __float2bfloat16(v - __bfloat162float(h));
        size_t o = zo + (size_t)(c0 + ty + i) * R + r0 + tx;
        hi[o] = h;
        lo[o] = l;
    }
}

// ---------------------------------------------------------------------------
// Row softmax (BETA folded) fused with bf16 hi/lo split output
// ---------------------------------------------------------------------------
__global__ void __launch_bounds__(256) softmax_split(
    const float* __restrict__ S, __nv_bfloat16* __restrict__ Ah,
    __nv_bfloat16* __restrict__ Al)
{
    __shared__ float red[256];
    const int t = threadIdx.x;
    const size_t base = (size_t)blockIdx.x * SEQ;
    const float* p = S + base;

    float4 v0 = *(const float4*)(p + t * 4);
    float4 v1 = *(const float4*)(p + 1024 + t * 4);
    v0.x *= BETA; v0.y *= BETA; v0.z *= BETA; v0.w *= BETA;
    v1.x *= BETA; v1.y *= BETA; v1.z *= BETA; v1.w *= BETA;

    float m = fmaxf(fmaxf(fmaxf(v0.x, v0.y), fmaxf(v0.z, v0.w)),
                    fmaxf(fmaxf(v1.x, v1.y), fmaxf(v1.z, v1.w)));
    red[t] = m;
    __syncthreads();
    for (int s = 128; s > 0; s >>= 1) {
        if (t < s) red[t] = fmaxf(red[t], red[t + s]);
        __syncthreads();
    }
    m = red[0];
    __syncthreads();

    v0.x = __expf(v0.x - m); v0.y = __expf(v0.y - m);
    v0.z = __expf(v0.z - m); v0.w = __expf(v0.w - m);
    v1.x = __expf(v1.x - m); v1.y = __expf(v1.y - m);
    v1.z = __expf(v1.z - m); v1.w = __expf(v1.w - m);

    float sum = (v0.x + v0.y) + (v0.z + v0.w) + (v1.x + v1.y) + (v1.z + v1.w);
    red[t] = sum;
    __syncthreads();
    for (int s = 128; s > 0; s >>= 1) {
        if (t < s) red[t] += red[t + s];
        __syncthreads();
    }
    const float inv = 1.0f / red[0];

    float vv[8] = { v0.x * inv, v0.y * inv, v0.z * inv, v0.w * inv,
                    v1.x * inv, v1.y * inv, v1.z * inv, v1.w * inv };
    const size_t off[2] = { base + t * 4, base + 1024 + t * 4 };
#pragma unroll
    for (int g = 0; g < 2; g++) {
#pragma unroll
        for (int j = 0; j < 4; j += 2) {
            __nv_bfloat162 hh, ll;
            bf_split2(vv[g * 4 + j], vv[g * 4 + j + 1], hh, ll);
            *(__nv_bfloat162*)(Ah + off[g] + j) = hh;
            *(__nv_bfloat162*)(Al + off[g] + j) = ll;
        }
    }
}

// ---------------------------------------------------------------------------
// Launch
// ---------------------------------------------------------------------------
extern "C" void kernel_launch(void* const* d_in, const int* in_sizes, int n_in,
                              void* d_out, int out_size)
{
    const float* query = (const float*)d_in[0];
    const float* key   = (const float*)d_in[1];
    const float* value = (const float*)d_in[2];
    const float* Wq    = (const float*)d_in[3];
    const float* bq    = (const float*)d_in[4];
    const float* Wk    = (const float*)d_in[5];
    const float* bk    = (const float*)d_in[6];
    const float* Wv    = (const float*)d_in[7];
    const float* bv    = (const float*)d_in[8];
    float* out = (float*)d_out;

    __nv_bfloat16 *xh, *xl, *wh, *wl, *qh, *ql, *kh, *kl, *vth, *vtl, *ah, *al;
    float *vf, *sf;
    cudaGetSymbolAddress((void**)&xh, g_xh);
    cudaGetSymbolAddress((void**)&xl, g_xl);
    cudaGetSymbolAddress((void**)&wh, g_wh);
    cudaGetSymbolAddress((void**)&wl, g_wl);
    cudaGetSymbolAddress((void**)&qh, g_qh);
    cudaGetSymbolAddress((void**)&ql, g_ql);
    cudaGetSymbolAddress((void**)&kh, g_kh);
    cudaGetSymbolAddress((void**)&kl, g_kl);
    cudaGetSymbolAddress((void**)&vf, g_vf);
    cudaGetSymbolAddress((void**)&vth, g_vth);
    cudaGetSymbolAddress((void**)&vtl, g_vtl);
    cudaGetSymbolAddress((void**)&sf, g_sf);
    cudaGetSymbolAddress((void**)&ah, g_ah);
    cudaGetSymbolAddress((void**)&al, g_al);

    cudaFuncSetAttribute((const void*)gemm_tc<0>,
                         cudaFuncAttributeMaxDynamicSharedMemorySize, SMEM_TOTAL);
    cudaFuncSetAttribute((const void*)gemm_tc<1>,
                         cudaFuncAttributeMaxDynamicSharedMemorySize, SMEM_TOTAL);
    cudaFuncSetAttribute((const void*)gemm_tc<2>,
                         cudaFuncAttributeMaxDynamicSharedMemorySize, SMEM_TOTAL);

    const int nIn4 = MTOT * DIM / 4;
    const dim3 wtGrid(DIM / 32, DIM / 32, 1);
    const dim3 projGrid(DIM / 128, MTOT / 128, 1);

    // ---- Q projection: epilogue emits bf16 hi/lo directly ----
    split_transpose<<<wtGrid, dim3(32, 8)>>>(Wq, wh, wl, DIM, DIM);
    split_kernel<<<nIn4 / 256, 256>>>(query, xh, xl, nIn4);
    gemm_tc<2><<<projGrid, 256, SMEM_TOTAL>>>(xh, xl, 0, wh, wl, 0, bq,
                                              nullptr, qh, ql, 0, DIM, DIM);

    // ---- K projection ----
    split_transpose<<<wtGrid, dim3(32, 8)>>>(Wk, wh, wl, DIM, DIM);
    split_kernel<<<nIn4 / 256, 256>>>(key, xh, xl, nIn4);
    gemm_tc<2><<<projGrid, 256, SMEM_TOTAL>>>(xh, xl, 0, wh, wl, 0, bk,
                                              nullptr, kh, kl, 0, DIM, DIM);

    // ---- V projection (fp32 out, then split+transpose to [D][S]) ----
    split_transpose<<<wtGrid, dim3(32, 8)>>>(Wv, wh, wl, DIM, DIM);
    split_kernel<<<nIn4 / 256, 256>>>(value, xh, xl, nIn4);
    gemm_tc<1><<<projGrid, 256, SMEM_TOTAL>>>(xh, xl, 0, wh, wl, 0, bv,
                                              vf, nullptr, nullptr, 0, DIM, DIM);
    split_transpose<<<dim3(DIM / 32, SEQ / 32, BATCH), dim3(32, 8)>>>(
        vf, vth, vtl, SEQ, DIM);

    // ---- Scores: sf[z] = q[z] @ k[z]^T (fp32) ----
    {
        dim3 grid(SEQ / 128, SEQ / 128, BATCH);
        gemm_tc<0><<<grid, 256, SMEM_TOTAL>>>(
            qh, ql, (long)SEQ * DIM, kh, kl, (long)SEQ * DIM, nullptr,
            sf, nullptr, nullptr, (long)SEQ * SEQ, DIM, SEQ);
    }

    // ---- Softmax (beta folded) fused with bf16 split ----
    softmax_split<<<BATCH * SEQ, 256>>>(sf, ah, al);

    // ---- Out: out[z] = A[z] @ v[z] ----
    {
        dim3 grid(DIM / 128, SEQ / 128, BATCH);
        gemm_tc<0><<<grid, 256, SMEM_TOTAL>>>(
            ah, al, (long)SEQ * SEQ, vth, vtl, (long)SEQ * DIM, nullptr,
            out, nullptr, nullptr, (long)SEQ * DIM, SEQ, DIM);
    }
}